// round 15
// baseline (speedup 1.0000x reference)
#include <cuda_runtime.h>
#include <cstdint>

// TranVectorQuantizer: latent [16384,8,32] f32, codebook [128,32] f32.
// Outputs concatenated in d_out (all f32):
//   [0,        4194304)  policy_vq_latent = latent + (quantized - latent)
//   [4194304,  8388608)  quantized_latent = codebook[argmin_j dist(x, c_j)]
//   [8388608, 75497472)  codebook_set = codebook tiled 16384x (16KB tiles)
//
// Distance reproduces the reference arithmetic EXACTLY (rel_err 0.0 verified
// R3/R4/R7/R8/R11/R12/R13): d_j = fmaf(-2, M_j, fl(A + B_j)), fixed f32x2 FMA
// chain order. DO NOT change the FMA chain order or the snapping add:
// tie-breaking on the ~ulp(32) distance grid depends on it.
//
// R14: the 256MB codebook_set broadcast is offloaded to TMA bulk copies
// (cp.async.bulk shared->global, 16 x 16KB per block from the SMEM-staged
// codebook), removing ~524K warp STG.128 instructions from the LSU/issue
// path. The TMA engines drain the writes concurrently with the argmin loop.
// VQ is the R4-proven 1-row/thread shape + coalesced smem-bi epilogue.

#define DDIM 32
#define KCODES 128
#define TILE_BYTES (KCODES * DDIM * 4)   // 16384

static __device__ __forceinline__ void upk2(unsigned long long p, float& a, float& b) {
    asm("mov.b64 {%0, %1}, %2;" : "=f"(a), "=f"(b) : "l"(p));
}
static __device__ __forceinline__ unsigned long long pk2(float a, float b) {
    unsigned long long r;
    asm("mov.b64 %0, {%1, %2};" : "=l"(r) : "f"(a), "f"(b));
    return r;
}
static __device__ __forceinline__ void fma2(unsigned long long& acc,
                                            unsigned long long x,
                                            unsigned long long c) {
    asm("fma.rn.f32x2 %0, %1, %2, %0;" : "+l"(acc) : "l"(x), "l"(c));
}
static __device__ __forceinline__ uint32_t smem_u32(const void* p) {
    uint32_t a;
    asm("{ .reg .u64 t; cvta.to.shared.u64 t, %1; cvt.u32.u64 %0, t; }"
        : "=r"(a) : "l"(p));
    return a;
}
static __device__ __forceinline__ void bulk_st(void* gdst, uint32_t ssrc, int bytes) {
    asm volatile("cp.async.bulk.global.shared::cta.bulk_group [%0], [%1], %2;"
        :: "l"(gdst), "r"(ssrc), "r"(bytes) : "memory");
}

// ---- exact kernel: n_rows == 131072; grid 1024 x 128, 1 row/thread ---------
__global__ void __launch_bounds__(128, 8) vq_tma_kernel(
    const float* __restrict__ latent,
    const float* __restrict__ cb,
    float* __restrict__ out,
    int n_rows)
{
    __shared__ __align__(16) float s_cb[KCODES * DDIM];   // 16 KB, TMA source
    __shared__ float s_nrm[KCODES];
    __shared__ int   s_bi[128];

    const int tid  = threadIdx.x;
    const int bid  = blockIdx.x;
    const int gtid = bid * 128 + tid;

    // ---- latent row loads issued early (overlap codebook staging) ----
    float4 xv[8];
    const float4* xr4 = reinterpret_cast<const float4*>(latent) + (size_t)gtid * 8;
    #pragma unroll
    for (int k = 0; k < 8; k++) xv[k] = xr4[k];

    // ---- stage codebook into smem ----
    float4* s_cb4 = reinterpret_cast<float4*>(s_cb);
    const float4* cb4 = reinterpret_cast<const float4*>(cb);
    #pragma unroll
    for (int i = 0; i < 8; i++) s_cb4[tid + i * 128] = cb4[tid + i * 128];
    __syncthreads();

    // ---- TMA: 16 bulk copies of the 16KB tile -> codebook_set region ------
    const size_t n_lat = (size_t)n_rows * DDIM;
    char* cs_base = reinterpret_cast<char*>(out + 2 * n_lat);
    if (tid == 0) {
        asm volatile("fence.proxy.async.shared::cta;" ::: "memory");
        uint32_t src = smem_u32(s_cb);
        char* dst = cs_base + (size_t)bid * 16 * TILE_BYTES;
        #pragma unroll
        for (int t = 0; t < 16; t++)
            bulk_st(dst + (size_t)t * TILE_BYTES, src, TILE_BYTES);
        asm volatile("cp.async.bulk.commit_group;" ::: "memory");
    }

    // ---- codebook norms (same accumulation order as all passing versions) --
    {
        float s = 0.f;
        #pragma unroll
        for (int d = 0; d < DDIM; d++) { float v = s_cb[tid * DDIM + d]; s += v * v; }
        s_nrm[tid] = s;
    }
    __syncthreads();

    // ---- pack row + A = ||x||^2 (identical numerics to R4) ----
    unsigned long long xp0[8], xp1[8];
    float A;
    {
        float a0 = 0.f, a1 = 0.f, a2 = 0.f, a3 = 0.f;
        #pragma unroll
        for (int k = 0; k < 8; k++) {
            a0 = fmaf(xv[k].x, xv[k].x, a0);
            a1 = fmaf(xv[k].y, xv[k].y, a1);
            a2 = fmaf(xv[k].z, xv[k].z, a2);
            a3 = fmaf(xv[k].w, xv[k].w, a3);
            xp0[k] = pk2(xv[k].x, xv[k].y);
            xp1[k] = pk2(xv[k].z, xv[k].w);
        }
        A = (a0 + a1) + (a2 + a3);
    }

    // ---- argmin over 128 codes (verbatim bitwise-verified chain) ----------
    float best = 3.0e38f;
    int   bi   = 0;
    const ulonglong2* scb2 = reinterpret_cast<const ulonglong2*>(s_cb);
    #pragma unroll 2
    for (int j = 0; j < KCODES; j++) {
        unsigned long long acc0 = 0ull, acc1 = 0ull;
        const ulonglong2* cj = scb2 + j * 8;       // broadcast LDS
        #pragma unroll
        for (int k = 0; k < 8; k++) {
            ulonglong2 c = cj[k];
            fma2(acc0, xp0[k], c.x);
            fma2(acc1, xp1[k], c.y);
        }
        unsigned long long accs;
        asm("add.rn.f32x2 %0, %1, %2;" : "=l"(accs) : "l"(acc0), "l"(acc1));
        float lo, hi; upk2(accs, lo, hi);
        float M = lo + hi;                   // x . c_j
        float S = A + s_nrm[j];              // snapping add fl(A + B_j)
        float d = fmaf(-2.0f, M, S);         // fl(S - 2M), single rounding
        if (d < best) { best = d; bi = j; }  // strict <: first index on ties
    }

    // ---- coalesced epilogue (proven): smem bi handoff, x re-read from L2 ---
    s_bi[tid] = bi;
    __syncthreads();

    const size_t baseF4 = (size_t)bid * 128 * 8;
    const float4* lat4 = reinterpret_cast<const float4*>(latent) + baseF4;
    float4* op = reinterpret_cast<float4*>(out) + baseF4;
    float4* oq = reinterpret_cast<float4*>(out + n_lat) + baseF4;
    #pragma unroll
    for (int i = 0; i < 8; i++) {
        int f   = tid + i * 128;
        int row = f >> 3;
        int c   = f & 7;
        float4 q = s_cb4[s_bi[row] * 8 + c];
        float4 x = __ldg(lat4 + f);
        float4 p;
        p.x = x.x + (q.x - x.x);
        p.y = x.y + (q.y - x.y);
        p.z = x.z + (q.z - x.z);
        p.w = x.w + (q.w - x.w);
        __stcs(oq + f, q);
        __stcs(op + f, p);
    }

    // ---- drain TMA store group before block teardown ----
    if (tid == 0)
        asm volatile("cp.async.bulk.wait_group 0;" ::: "memory");
}

// ---------------- generic fallback: 1 row/thread (R4-proven) ----------------
__global__ void __launch_bounds__(128, 8) vq_fused1_kernel(
    const float* __restrict__ latent,
    const float* __restrict__ cb,
    float* __restrict__ out,
    int n_rows)
{
    __shared__ float s_cb[KCODES * DDIM];
    __shared__ float s_nrm[KCODES];

    const int tid  = threadIdx.x;
    const int gtid = blockIdx.x * 128 + tid;
    const bool active = gtid < n_rows;

    float4 xv[8];
    const float4* xr4 = reinterpret_cast<const float4*>(latent) + (size_t)gtid * 8;
    if (active) {
        #pragma unroll
        for (int k = 0; k < 8; k++) xv[k] = xr4[k];
    }

    float4* s_cb4 = reinterpret_cast<float4*>(s_cb);
    const float4* cb4 = reinterpret_cast<const float4*>(cb);
    #pragma unroll
    for (int i = 0; i < 8; i++) s_cb4[tid + i * 128] = cb4[tid + i * 128];
    __syncthreads();

    {
        float s = 0.f;
        #pragma unroll
        for (int d = 0; d < DDIM; d++) { float v = s_cb[tid * DDIM + d]; s += v * v; }
        s_nrm[tid] = s;
    }
    __syncthreads();

    const size_t n_lat = (size_t)n_rows * DDIM;
    float* out_quant = out + n_lat;
    float4* out_cs4  = reinterpret_cast<float4*>(out + 2 * n_lat);
    const size_t nth = (size_t)gridDim.x * 128;

    unsigned long long xp0[8], xp1[8];
    float A = 0.f;
    if (active) {
        float a0 = 0.f, a1 = 0.f, a2 = 0.f, a3 = 0.f;
        #pragma unroll
        for (int k = 0; k < 8; k++) {
            a0 = fmaf(xv[k].x, xv[k].x, a0);
            a1 = fmaf(xv[k].y, xv[k].y, a1);
            a2 = fmaf(xv[k].z, xv[k].z, a2);
            a3 = fmaf(xv[k].w, xv[k].w, a3);
            xp0[k] = pk2(xv[k].x, xv[k].y);
            xp1[k] = pk2(xv[k].z, xv[k].w);
        }
        A = (a0 + a1) + (a2 + a3);
    }

    const size_t total4 = (size_t)n_rows * 128;
    for (size_t i4 = (size_t)gtid; i4 < total4; i4 += nth)
        __stcs(&out_cs4[i4], s_cb4[i4 & 1023]);

    if (!active) return;

    float best = 3.0e38f;
    int   bi   = 0;
    const ulonglong2* scb2 = reinterpret_cast<const ulonglong2*>(s_cb);
    #pragma unroll 2
    for (int j = 0; j < KCODES; j++) {
        unsigned long long acc0 = 0ull, acc1 = 0ull;
        const ulonglong2* cj = scb2 + j * 8;
        #pragma unroll
        for (int k = 0; k < 8; k++) {
            ulonglong2 c = cj[k];
            fma2(acc0, xp0[k], c.x);
            fma2(acc1, xp1[k], c.y);
        }
        unsigned long long accs;
        asm("add.rn.f32x2 %0, %1, %2;" : "=l"(accs) : "l"(acc0), "l"(acc1));
        float lo, hi; upk2(accs, lo, hi);
        float d = fmaf(-2.0f, lo + hi, A + s_nrm[j]);
        if (d < best) { best = d; bi = j; }
    }

    const float4* q4 = reinterpret_cast<const float4*>(s_cb + bi * DDIM);
    float4* oq = reinterpret_cast<float4*>(out_quant) + (size_t)gtid * 8;
    float4* op = reinterpret_cast<float4*>(out)       + (size_t)gtid * 8;
    #pragma unroll
    for (int k = 0; k < 8; k++) {
        float4 q = q4[k];
        __stcs(oq + k, q);
        float xx, xy, xz, xw;
        upk2(xp0[k], xx, xy); upk2(xp1[k], xz, xw);
        float4 p;
        p.x = xx + (q.x - xx); p.y = xy + (q.y - xy);
        p.z = xz + (q.z - xz); p.w = xw + (q.w - xw);
        __stcs(op + k, p);
    }
}

extern "C" void kernel_launch(void* const* d_in, const int* in_sizes, int n_in,
                              void* d_out, int out_size)
{
    const float* latent = (const float*)d_in[0];
    const float* cb     = (const float*)d_in[1];
    int sz0 = in_sizes[0], sz1 = in_sizes[1];
    if (sz0 < sz1) {  // safety: latent is the big tensor
        const float* t = latent; latent = cb; cb = t;
        int ts = sz0; sz0 = sz1; sz1 = ts;
    }
    (void)n_in; (void)out_size;
    int n_rows = sz0 / DDIM;                         // 131072
    if (n_rows == 131072) {
        vq_tma_kernel<<<1024, 128>>>(latent, cb, (float*)d_out, n_rows);
    } else {
        vq_fused1_kernel<<<(n_rows + 127) / 128, 128>>>(latent, cb, (float*)d_out, n_rows);
    }
}

// round 16
// speedup vs baseline: 1.0706x; 1.0706x over previous
#include <cuda_runtime.h>
#include <cstdint>

// TranVectorQuantizer: latent [16384,8,32] f32, codebook [128,32] f32.
// Outputs concatenated in d_out (all f32):
//   [0,        4194304)  policy_vq_latent = latent + (quantized - latent)
//   [4194304,  8388608)  quantized_latent = codebook[argmin_j dist(x, c_j)]
//   [8388608, 75497472)  codebook_set = codebook tiled 16384x
//
// Distance reproduces the reference arithmetic EXACTLY (rel_err 0.0 verified
// R3..R15): d_j = fmaf(-2, M_j, fl(A + B_j)), fixed f32x2 FMA chain order.
// DO NOT change the FMA chain order or the snapping add: tie-breaking on the
// ~ulp(32) distance grid depends on it.
//
// R16: 4 rows/thread register blocking. Each broadcast codebook LDS.128 now
// feeds FOUR dot chains (0.0625 warp-instr per (row,code) vs 0.125 in R12),
// halving the dominant L1/smem-crossbar work again. 512 blocks x 64 threads,
// ~180 regs (cap 204 via __launch_bounds__(64,5)). Interleaved broadcast
// stores (4 per code) + coalesced smem-bi epilogue, both proven.

#define DDIM 32
#define KCODES 128

static __device__ __forceinline__ void upk2(unsigned long long p, float& a, float& b) {
    asm("mov.b64 {%0, %1}, %2;" : "=f"(a), "=f"(b) : "l"(p));
}
static __device__ __forceinline__ unsigned long long pk2(float a, float b) {
    unsigned long long r;
    asm("mov.b64 %0, {%1, %2};" : "=l"(r) : "f"(a), "f"(b));
    return r;
}
static __device__ __forceinline__ void fma2(unsigned long long& acc,
                                            unsigned long long x,
                                            unsigned long long c) {
    asm("fma.rn.f32x2 %0, %1, %2, %0;" : "+l"(acc) : "l"(x), "l"(c));
}

// ---- exact kernel: n_rows == 131072; grid 512 x 64, 4 rows/thread ----------
// Block owns rows [bid*256, bid*256+256); thread tid owns rows
// bid*256 + tid + {0, 64, 128, 192}.
__global__ void __launch_bounds__(64, 5) vq4_kernel(
    const float* __restrict__ latent,
    const float* __restrict__ cb,
    float* __restrict__ out,
    int n_rows)
{
    __shared__ float s_cb[KCODES * DDIM];   // 16 KB
    __shared__ float s_nrm[KCODES];
    __shared__ int   s_bi[256];

    const int tid = threadIdx.x;
    const int bid = blockIdx.x;
    const int gt  = bid * 64 + tid;          // 0..32767 (store-stream id)
    const int row0 = bid * 256 + tid;        // rows row0 + 64*r, r=0..3

    // ---- load 4 rows directly as f32x2 packs (bit-identical to float4) ----
    unsigned long long xp0[4][8], xp1[4][8];
    #pragma unroll
    for (int r = 0; r < 4; r++) {
        const ulonglong2* lr = reinterpret_cast<const ulonglong2*>(latent)
                             + (size_t)(row0 + 64 * r) * 8;
        #pragma unroll
        for (int k = 0; k < 8; k++) {
            ulonglong2 u = lr[k];
            xp0[r][k] = u.x;
            xp1[r][k] = u.y;
        }
    }

    // ---- stage codebook ----
    float4* s_cb4 = reinterpret_cast<float4*>(s_cb);
    const float4* cb4 = reinterpret_cast<const float4*>(cb);
    #pragma unroll
    for (int i = 0; i < 16; i++) s_cb4[tid + i * 64] = cb4[tid + i * 64];
    __syncthreads();

    #pragma unroll
    for (int h = 0; h < 2; h++) {    // same per-code accumulation order as always
        int c = tid + h * 64;
        float s = 0.f;
        #pragma unroll
        for (int d = 0; d < DDIM; d++) { float v = s_cb[c * DDIM + d]; s += v * v; }
        s_nrm[c] = s;
    }
    __syncthreads();

    // ---- A = ||x||^2 per row: unpack packs, EXACT original fmaf order ------
    float A[4];
    #pragma unroll
    for (int r = 0; r < 4; r++) {
        float a0 = 0.f, a1 = 0.f, a2 = 0.f, a3 = 0.f;
        #pragma unroll
        for (int k = 0; k < 8; k++) {
            float x0, x1, x2, x3;
            upk2(xp0[r][k], x0, x1); upk2(xp1[r][k], x2, x3);
            a0 = fmaf(x0, x0, a0); a1 = fmaf(x1, x1, a1);
            a2 = fmaf(x2, x2, a2); a3 = fmaf(x3, x3, a3);
        }
        A[r] = (a0 + a1) + (a2 + a3);
    }

    const size_t n_lat = (size_t)n_rows * DDIM;
    float4* out_cs4 = reinterpret_cast<float4*>(out + 2 * n_lat);
    const size_t nth = (size_t)gridDim.x * 64;     // 32768, multiple of 1024

    float best[4];
    int   bi[4];
    #pragma unroll
    for (int r = 0; r < 4; r++) { best[r] = 3.0e38f; bi[r] = 0; }

    const ulonglong2* scb2 = reinterpret_cast<const ulonglong2*>(s_cb);

    // stride preserves (index & 1023): one register-held broadcast value
    float4 vbc = s_cb4[gt & 1023];
    float4* csp = out_cs4 + gt;

    for (int j = 0; j < KCODES; j++) {
        // 4 interleaved codebook_set stores (512 per thread total = exact)
        __stcs(csp, vbc);
        __stcs(csp + nth, vbc);
        __stcs(csp + 2 * nth, vbc);
        __stcs(csp + 3 * nth, vbc);
        csp += 4 * nth;

        unsigned long long a0[4], a1[4];
        #pragma unroll
        for (int r = 0; r < 4; r++) { a0[r] = 0ull; a1[r] = 0ull; }
        const ulonglong2* cj = scb2 + j * 8;   // broadcast LDS, shared by 4 rows
        #pragma unroll
        for (int k = 0; k < 8; k++) {
            ulonglong2 c = cj[k];
            #pragma unroll
            for (int r = 0; r < 4; r++) {
                fma2(a0[r], xp0[r][k], c.x);
                fma2(a1[r], xp1[r][k], c.y);
            }
        }
        float nrm = s_nrm[j];
        #pragma unroll
        for (int r = 0; r < 4; r++) {
            unsigned long long s;
            asm("add.rn.f32x2 %0, %1, %2;" : "=l"(s) : "l"(a0[r]), "l"(a1[r]));
            float lo, hi; upk2(s, lo, hi);
            float d = fmaf(-2.0f, lo + hi, A[r] + nrm);  // fl(S - 2M), single rounding
            if (d < best[r]) { best[r] = d; bi[r] = j; } // strict <: first index on ties
        }
    }

    // ---- coalesced epilogue (proven): smem bi handoff, x re-read from L2 ---
    #pragma unroll
    for (int r = 0; r < 4; r++) s_bi[tid + 64 * r] = bi[r];
    __syncthreads();

    const size_t baseF4 = (size_t)bid * 256 * 8;   // block's first float4 (2048/block)
    const float4* lat4 = reinterpret_cast<const float4*>(latent) + baseF4;
    float4* op = reinterpret_cast<float4*>(out) + baseF4;
    float4* oq = reinterpret_cast<float4*>(out + n_lat) + baseF4;
    #pragma unroll 8
    for (int i = 0; i < 32; i++) {
        int f   = tid + i * 64;
        int row = f >> 3;
        int c   = f & 7;
        float4 q = s_cb4[s_bi[row] * 8 + c];
        float4 x = __ldg(lat4 + f);
        float4 p;
        p.x = x.x + (q.x - x.x);
        p.y = x.y + (q.y - x.y);
        p.z = x.z + (q.z - x.z);
        p.w = x.w + (q.w - x.w);
        __stcs(oq + f, q);
        __stcs(op + f, p);
    }
}

// ---------------- generic fallback: 1 row/thread (R4-proven) ----------------
__global__ void __launch_bounds__(128, 8) vq_fused1_kernel(
    const float* __restrict__ latent,
    const float* __restrict__ cb,
    float* __restrict__ out,
    int n_rows)
{
    __shared__ float s_cb[KCODES * DDIM];
    __shared__ float s_nrm[KCODES];

    const int tid  = threadIdx.x;
    const int gtid = blockIdx.x * 128 + tid;
    const bool active = gtid < n_rows;

    float4 xv[8];
    const float4* xr4 = reinterpret_cast<const float4*>(latent) + (size_t)gtid * 8;
    if (active) {
        #pragma unroll
        for (int k = 0; k < 8; k++) xv[k] = xr4[k];
    }

    float4* s_cb4 = reinterpret_cast<float4*>(s_cb);
    const float4* cb4 = reinterpret_cast<const float4*>(cb);
    #pragma unroll
    for (int i = 0; i < 8; i++) s_cb4[tid + i * 128] = cb4[tid + i * 128];
    __syncthreads();

    {
        float s = 0.f;
        #pragma unroll
        for (int d = 0; d < DDIM; d++) { float v = s_cb[tid * DDIM + d]; s += v * v; }
        s_nrm[tid] = s;
    }
    __syncthreads();

    const size_t n_lat = (size_t)n_rows * DDIM;
    float* out_quant = out + n_lat;
    float4* out_cs4  = reinterpret_cast<float4*>(out + 2 * n_lat);
    const size_t nth = (size_t)gridDim.x * 128;

    unsigned long long xp0[8], xp1[8];
    float A = 0.f;
    if (active) {
        float a0 = 0.f, a1 = 0.f, a2 = 0.f, a3 = 0.f;
        #pragma unroll
        for (int k = 0; k < 8; k++) {
            a0 = fmaf(xv[k].x, xv[k].x, a0);
            a1 = fmaf(xv[k].y, xv[k].y, a1);
            a2 = fmaf(xv[k].z, xv[k].z, a2);
            a3 = fmaf(xv[k].w, xv[k].w, a3);
            xp0[k] = pk2(xv[k].x, xv[k].y);
            xp1[k] = pk2(xv[k].z, xv[k].w);
        }
        A = (a0 + a1) + (a2 + a3);
    }

    const size_t total4 = (size_t)n_rows * 128;
    for (size_t i4 = (size_t)gtid; i4 < total4; i4 += nth)
        __stcs(&out_cs4[i4], s_cb4[i4 & 1023]);

    if (!active) return;

    float best = 3.0e38f;
    int   bi   = 0;
    const ulonglong2* scb2 = reinterpret_cast<const ulonglong2*>(s_cb);
    #pragma unroll 2
    for (int j = 0; j < KCODES; j++) {
        unsigned long long acc0 = 0ull, acc1 = 0ull;
        const ulonglong2* cj = scb2 + j * 8;
        #pragma unroll
        for (int k = 0; k < 8; k++) {
            ulonglong2 c = cj[k];
            fma2(acc0, xp0[k], c.x);
            fma2(acc1, xp1[k], c.y);
        }
        unsigned long long accs;
        asm("add.rn.f32x2 %0, %1, %2;" : "=l"(accs) : "l"(acc0), "l"(acc1));
        float lo, hi; upk2(accs, lo, hi);
        float d = fmaf(-2.0f, lo + hi, A + s_nrm[j]);
        if (d < best) { best = d; bi = j; }
    }

    const float4* q4 = reinterpret_cast<const float4*>(s_cb + bi * DDIM);
    float4* oq = reinterpret_cast<float4*>(out_quant) + (size_t)gtid * 8;
    float4* op = reinterpret_cast<float4*>(out)       + (size_t)gtid * 8;
    #pragma unroll
    for (int k = 0; k < 8; k++) {
        float4 q = q4[k];
        __stcs(oq + k, q);
        float xx, xy, xz, xw;
        upk2(xp0[k], xx, xy); upk2(xp1[k], xz, xw);
        float4 p;
        p.x = xx + (q.x - xx); p.y = xy + (q.y - xy);
        p.z = xz + (q.z - xz); p.w = xw + (q.w - xw);
        __stcs(op + k, p);
    }
}

extern "C" void kernel_launch(void* const* d_in, const int* in_sizes, int n_in,
                              void* d_out, int out_size)
{
    const float* latent = (const float*)d_in[0];
    const float* cb     = (const float*)d_in[1];
    int sz0 = in_sizes[0], sz1 = in_sizes[1];
    if (sz0 < sz1) {  // safety: latent is the big tensor
        const float* t = latent; latent = cb; cb = t;
        int ts = sz0; sz0 = sz1; sz1 = ts;
    }
    (void)n_in; (void)out_size;
    int n_rows = sz0 / DDIM;                         // 131072
    if (n_rows == 131072) {
        vq4_kernel<<<512, 64>>>(latent, cb, (float*)d_out, n_rows);
    } else {
        vq_fused1_kernel<<<(n_rows + 127) / 128, 128>>>(latent, cb, (float*)d_out, n_rows);
    }
}

// round 17
// speedup vs baseline: 1.0887x; 1.0169x over previous
#include <cuda_runtime.h>
#include <cstdint>

// TranVectorQuantizer: latent [16384,8,32] f32, codebook [128,32] f32.
// Outputs concatenated in d_out (all f32):
//   [0,        4194304)  policy_vq_latent = latent + (quantized - latent)
//   [4194304,  8388608)  quantized_latent = codebook[argmin_j dist(x, c_j)]
//   [8388608, 75497472)  codebook_set = codebook tiled 16384x
//
// Distance reproduces the reference arithmetic EXACTLY (rel_err 0.0 verified
// R3..R15): d_j = fmaf(-2, M_j, fl(A + B_j)), fixed f32x2 FMA chain order.
// DO NOT change the FMA chain order or the snapping add: tie-breaking on the
// ~ulp(32) distance grid depends on it.
//
// R16: 4 rows/thread register blocking. Each broadcast codebook LDS.128 now
// feeds FOUR dot chains (0.0625 warp-instr per (row,code) vs 0.125 in R12),
// halving the dominant L1/smem-crossbar work again. 512 blocks x 64 threads,
// ~180 regs (cap 204 via __launch_bounds__(64,5)). Interleaved broadcast
// stores (4 per code) + coalesced smem-bi epilogue, both proven.

#define DDIM 32
#define KCODES 128

static __device__ __forceinline__ void upk2(unsigned long long p, float& a, float& b) {
    asm("mov.b64 {%0, %1}, %2;" : "=f"(a), "=f"(b) : "l"(p));
}
static __device__ __forceinline__ unsigned long long pk2(float a, float b) {
    unsigned long long r;
    asm("mov.b64 %0, {%1, %2};" : "=l"(r) : "f"(a), "f"(b));
    return r;
}
static __device__ __forceinline__ void fma2(unsigned long long& acc,
                                            unsigned long long x,
                                            unsigned long long c) {
    asm("fma.rn.f32x2 %0, %1, %2, %0;" : "+l"(acc) : "l"(x), "l"(c));
}

// ---- exact kernel: n_rows == 131072; grid 512 x 64, 4 rows/thread ----------
// Block owns rows [bid*256, bid*256+256); thread tid owns rows
// bid*256 + tid + {0, 64, 128, 192}.
__global__ void __launch_bounds__(64, 5) vq4_kernel(
    const float* __restrict__ latent,
    const float* __restrict__ cb,
    float* __restrict__ out,
    int n_rows)
{
    __shared__ float s_cb[KCODES * DDIM];   // 16 KB
    __shared__ float s_nrm[KCODES];
    __shared__ int   s_bi[256];

    const int tid = threadIdx.x;
    const int bid = blockIdx.x;
    const int gt  = bid * 64 + tid;          // 0..32767 (store-stream id)
    const int row0 = bid * 256 + tid;        // rows row0 + 64*r, r=0..3

    // ---- load 4 rows directly as f32x2 packs (bit-identical to float4) ----
    unsigned long long xp0[4][8], xp1[4][8];
    #pragma unroll
    for (int r = 0; r < 4; r++) {
        const ulonglong2* lr = reinterpret_cast<const ulonglong2*>(latent)
                             + (size_t)(row0 + 64 * r) * 8;
        #pragma unroll
        for (int k = 0; k < 8; k++) {
            ulonglong2 u = lr[k];
            xp0[r][k] = u.x;
            xp1[r][k] = u.y;
        }
    }

    // ---- stage codebook ----
    float4* s_cb4 = reinterpret_cast<float4*>(s_cb);
    const float4* cb4 = reinterpret_cast<const float4*>(cb);
    #pragma unroll
    for (int i = 0; i < 16; i++) s_cb4[tid + i * 64] = cb4[tid + i * 64];
    __syncthreads();

    #pragma unroll
    for (int h = 0; h < 2; h++) {    // same per-code accumulation order as always
        int c = tid + h * 64;
        float s = 0.f;
        #pragma unroll
        for (int d = 0; d < DDIM; d++) { float v = s_cb[c * DDIM + d]; s += v * v; }
        s_nrm[c] = s;
    }
    __syncthreads();

    // ---- A = ||x||^2 per row: unpack packs, EXACT original fmaf order ------
    float A[4];
    #pragma unroll
    for (int r = 0; r < 4; r++) {
        float a0 = 0.f, a1 = 0.f, a2 = 0.f, a3 = 0.f;
        #pragma unroll
        for (int k = 0; k < 8; k++) {
            float x0, x1, x2, x3;
            upk2(xp0[r][k], x0, x1); upk2(xp1[r][k], x2, x3);
            a0 = fmaf(x0, x0, a0); a1 = fmaf(x1, x1, a1);
            a2 = fmaf(x2, x2, a2); a3 = fmaf(x3, x3, a3);
        }
        A[r] = (a0 + a1) + (a2 + a3);
    }

    const size_t n_lat = (size_t)n_rows * DDIM;
    float4* out_cs4 = reinterpret_cast<float4*>(out + 2 * n_lat);
    const size_t nth = (size_t)gridDim.x * 64;     // 32768, multiple of 1024

    float best[4];
    int   bi[4];
    #pragma unroll
    for (int r = 0; r < 4; r++) { best[r] = 3.0e38f; bi[r] = 0; }

    const ulonglong2* scb2 = reinterpret_cast<const ulonglong2*>(s_cb);

    // stride preserves (index & 1023): one register-held broadcast value
    float4 vbc = s_cb4[gt & 1023];
    float4* csp = out_cs4 + gt;

    for (int j = 0; j < KCODES; j++) {
        // 4 interleaved codebook_set stores (512 per thread total = exact)
        __stcs(csp, vbc);
        __stcs(csp + nth, vbc);
        __stcs(csp + 2 * nth, vbc);
        __stcs(csp + 3 * nth, vbc);
        csp += 4 * nth;

        unsigned long long a0[4], a1[4];
        #pragma unroll
        for (int r = 0; r < 4; r++) { a0[r] = 0ull; a1[r] = 0ull; }
        const ulonglong2* cj = scb2 + j * 8;   // broadcast LDS, shared by 4 rows
        #pragma unroll
        for (int k = 0; k < 8; k++) {
            ulonglong2 c = cj[k];
            #pragma unroll
            for (int r = 0; r < 4; r++) {
                fma2(a0[r], xp0[r][k], c.x);
                fma2(a1[r], xp1[r][k], c.y);
            }
        }
        float nrm = s_nrm[j];
        #pragma unroll
        for (int r = 0; r < 4; r++) {
            unsigned long long s;
            asm("add.rn.f32x2 %0, %1, %2;" : "=l"(s) : "l"(a0[r]), "l"(a1[r]));
            float lo, hi; upk2(s, lo, hi);
            float d = fmaf(-2.0f, lo + hi, A[r] + nrm);  // fl(S - 2M), single rounding
            if (d < best[r]) { best[r] = d; bi[r] = j; } // strict <: first index on ties
        }
    }

    // ---- coalesced epilogue (proven): smem bi handoff, x re-read from L2 ---
    #pragma unroll
    for (int r = 0; r < 4; r++) s_bi[tid + 64 * r] = bi[r];
    __syncthreads();

    const size_t baseF4 = (size_t)bid * 256 * 8;   // block's first float4 (2048/block)
    const float4* lat4 = reinterpret_cast<const float4*>(latent) + baseF4;
    float4* op = reinterpret_cast<float4*>(out) + baseF4;
    float4* oq = reinterpret_cast<float4*>(out + n_lat) + baseF4;
    #pragma unroll 8
    for (int i = 0; i < 32; i++) {
        int f   = tid + i * 64;
        int row = f >> 3;
        int c   = f & 7;
        float4 q = s_cb4[s_bi[row] * 8 + c];
        float4 x = __ldg(lat4 + f);
        float4 p;
        p.x = x.x + (q.x - x.x);
        p.y = x.y + (q.y - x.y);
        p.z = x.z + (q.z - x.z);
        p.w = x.w + (q.w - x.w);
        __stcs(oq + f, q);
        __stcs(op + f, p);
    }
}

// ---------------- generic fallback: 1 row/thread (R4-proven) ----------------
__global__ void __launch_bounds__(128, 8) vq_fused1_kernel(
    const float* __restrict__ latent,
    const float* __restrict__ cb,
    float* __restrict__ out,
    int n_rows)
{
    __shared__ float s_cb[KCODES * DDIM];
    __shared__ float s_nrm[KCODES];

    const int tid  = threadIdx.x;
    const int gtid = blockIdx.x * 128 + tid;
    const bool active = gtid < n_rows;

    float4 xv[8];
    const float4* xr4 = reinterpret_cast<const float4*>(latent) + (size_t)gtid * 8;
    if (active) {
        #pragma unroll
        for (int k = 0; k < 8; k++) xv[k] = xr4[k];
    }

    float4* s_cb4 = reinterpret_cast<float4*>(s_cb);
    const float4* cb4 = reinterpret_cast<const float4*>(cb);
    #pragma unroll
    for (int i = 0; i < 8; i++) s_cb4[tid + i * 128] = cb4[tid + i * 128];
    __syncthreads();

    {
        float s = 0.f;
        #pragma unroll
        for (int d = 0; d < DDIM; d++) { float v = s_cb[tid * DDIM + d]; s += v * v; }
        s_nrm[tid] = s;
    }
    __syncthreads();

    const size_t n_lat = (size_t)n_rows * DDIM;
    float* out_quant = out + n_lat;
    float4* out_cs4  = reinterpret_cast<float4*>(out + 2 * n_lat);
    const size_t nth = (size_t)gridDim.x * 128;

    unsigned long long xp0[8], xp1[8];
    float A = 0.f;
    if (active) {
        float a0 = 0.f, a1 = 0.f, a2 = 0.f, a3 = 0.f;
        #pragma unroll
        for (int k = 0; k < 8; k++) {
            a0 = fmaf(xv[k].x, xv[k].x, a0);
            a1 = fmaf(xv[k].y, xv[k].y, a1);
            a2 = fmaf(xv[k].z, xv[k].z, a2);
            a3 = fmaf(xv[k].w, xv[k].w, a3);
            xp0[k] = pk2(xv[k].x, xv[k].y);
            xp1[k] = pk2(xv[k].z, xv[k].w);
        }
        A = (a0 + a1) + (a2 + a3);
    }

    const size_t total4 = (size_t)n_rows * 128;
    for (size_t i4 = (size_t)gtid; i4 < total4; i4 += nth)
        __stcs(&out_cs4[i4], s_cb4[i4 & 1023]);

    if (!active) return;

    float best = 3.0e38f;
    int   bi   = 0;
    const ulonglong2* scb2 = reinterpret_cast<const ulonglong2*>(s_cb);
    #pragma unroll 2
    for (int j = 0; j < KCODES; j++) {
        unsigned long long acc0 = 0ull, acc1 = 0ull;
        const ulonglong2* cj = scb2 + j * 8;
        #pragma unroll
        for (int k = 0; k < 8; k++) {
            ulonglong2 c = cj[k];
            fma2(acc0, xp0[k], c.x);
            fma2(acc1, xp1[k], c.y);
        }
        unsigned long long accs;
        asm("add.rn.f32x2 %0, %1, %2;" : "=l"(accs) : "l"(acc0), "l"(acc1));
        float lo, hi; upk2(accs, lo, hi);
        float d = fmaf(-2.0f, lo + hi, A + s_nrm[j]);
        if (d < best) { best = d; bi = j; }
    }

    const float4* q4 = reinterpret_cast<const float4*>(s_cb + bi * DDIM);
    float4* oq = reinterpret_cast<float4*>(out_quant) + (size_t)gtid * 8;
    float4* op = reinterpret_cast<float4*>(out)       + (size_t)gtid * 8;
    #pragma unroll
    for (int k = 0; k < 8; k++) {
        float4 q = q4[k];
        __stcs(oq + k, q);
        float xx, xy, xz, xw;
        upk2(xp0[k], xx, xy); upk2(xp1[k], xz, xw);
        float4 p;
        p.x = xx + (q.x - xx); p.y = xy + (q.y - xy);
        p.z = xz + (q.z - xz); p.w = xw + (q.w - xw);
        __stcs(op + k, p);
    }
}

extern "C" void kernel_launch(void* const* d_in, const int* in_sizes, int n_in,
                              void* d_out, int out_size)
{
    const float* latent = (const float*)d_in[0];
    const float* cb     = (const float*)d_in[1];
    int sz0 = in_sizes[0], sz1 = in_sizes[1];
    if (sz0 < sz1) {  // safety: latent is the big tensor
        const float* t = latent; latent = cb; cb = t;
        int ts = sz0; sz0 = sz1; sz1 = ts;
    }
    (void)n_in; (void)out_size;
    int n_rows = sz0 / DDIM;                         // 131072
    if (n_rows == 131072) {
        vq4_kernel<<<512, 64>>>(latent, cb, (float*)d_out, n_rows);
    } else {
        vq_fused1_kernel<<<(n_rows + 127) / 128, 128>>>(latent, cb, (float*)d_out, n_rows);
    }
}